// round 14
// baseline (speedup 1.0000x reference)
#include <cuda_runtime.h>
#include <cuda_fp16.h>
#include <math.h>
#include <cstdint>

#define BB 32
#define NN 1024
#define IND 64
#define ATTN 128
#define OUTD 64
#define CTOT 320   // Q(128) | K(128) | V(64)

// ---------------- scratch (device globals; no allocations allowed) ----------
__device__ float  g_deg[BB * NN];
__device__ float  g_diag[BB * NN];
__device__ __half g_adjh[(size_t)BB * NN * NN]; // half adj copy, 67 MB
__device__ float  g_H[(size_t)BB * NN * CTOT];  // fp32 row-major (correction term)
__device__ __half g_Hth[(size_t)BB * CTOT * NN];// half, feature-major (GEMM B)
__device__ __half g_Qh[(size_t)BB * NN * ATTN]; // half, PRE-SCALED by 1/8
__device__ __half g_Kh[(size_t)BB * NN * ATTN]; // half

// ---------------- helpers ----------------------------------------------------
__device__ __forceinline__ void mma_f16(float c[4],
                                        uint32_t a0, uint32_t a1, uint32_t a2, uint32_t a3,
                                        uint32_t b0, uint32_t b1) {
    asm volatile(
        "mma.sync.aligned.m16n8k16.row.col.f32.f16.f16.f32 "
        "{%0,%1,%2,%3}, {%4,%5,%6,%7}, {%8,%9}, {%0,%1,%2,%3};\n"
        : "+f"(c[0]), "+f"(c[1]), "+f"(c[2]), "+f"(c[3])
        : "r"(a0), "r"(a1), "r"(a2), "r"(a3), "r"(b0), "r"(b1));
}

__device__ __forceinline__ void ldsm_x4(uint32_t& r0, uint32_t& r1,
                                        uint32_t& r2, uint32_t& r3, uint32_t addr) {
    asm volatile("ldmatrix.sync.aligned.m8n8.x4.shared.b16 {%0,%1,%2,%3}, [%4];"
                 : "=r"(r0), "=r"(r1), "=r"(r2), "=r"(r3) : "r"(addr));
}
__device__ __forceinline__ void ldsm_x2(uint32_t& r0, uint32_t& r1, uint32_t addr) {
    asm volatile("ldmatrix.sync.aligned.m8n8.x2.shared.b16 {%0,%1}, [%2];"
                 : "=r"(r0), "=r"(r1) : "r"(addr));
}

__device__ __forceinline__ void cp16(uint32_t dst, const void* src) {
    asm volatile("cp.async.ca.shared.global [%0], [%1], 16;" :: "r"(dst), "l"(src));
}
__device__ __forceinline__ uint32_t smem_u32(const void* p) {
    uint32_t a;
    asm("{ .reg .u64 t; cvta.to.shared.u64 t, %1; cvt.u32.u64 %0, t; }" : "=r"(a) : "l"(p));
    return a;
}
__device__ __forceinline__ uint32_t h2u(__half2 h) {
    return *reinterpret_cast<uint32_t*>(&h);
}

// ---------------- kernel A: degrees + diag + half adj copy -------------------
__global__ void __launch_bounds__(256) deg_kernel(const float* __restrict__ adj) {
    int warp = (blockIdx.x * blockDim.x + threadIdx.x) >> 5;
    int lane = threadIdx.x & 31;
    if (warp >= BB * NN) return;
    const float* row = adj + (size_t)warp * NN;
    const float4* r4 = (const float4*)row;
    __half* hrow = g_adjh + (size_t)warp * NN;
    float s = 0.f;
#pragma unroll
    for (int j = lane; j < NN / 4; j += 32) {
        float4 v = r4[j];
        s += (v.x + v.y) + (v.z + v.w);
        __half2 h01 = __floats2half2_rn(v.x, v.y);
        __half2 h23 = __floats2half2_rn(v.z, v.w);
        uint2 u; u.x = h2u(h01); u.y = h2u(h23);
        *(uint2*)(hrow + 4 * j) = u;
    }
#pragma unroll
    for (int o = 16; o; o >>= 1) s += __shfl_xor_sync(0xffffffffu, s, o);
    if (lane == 0) {
        int i = warp & (NN - 1);
        float dg = row[i];
        float rs = s - dg + 1.0f;
        g_deg[warp]  = rsqrtf(fmaxf(rs, 1.0f));
        g_diag[warp] = dg;
    }
}

// ---------------- kernel B: H' = diag(d) * (x @ [Wq|Wk|Wv]) ------------------
__global__ void __launch_bounds__(320) h_kernel(const float* __restrict__ x,
                                                const float* __restrict__ Wq,
                                                const float* __restrict__ Wk,
                                                const float* __restrict__ Wv) {
    __shared__ float xs[64][IND];
    int b = blockIdx.y;
    int rb = blockIdx.x;
    int t = threadIdx.x;
    size_t rowbase = ((size_t)b * NN + rb * 64);

    for (int idx = t; idx < 64 * IND; idx += 320) {
        int r = idx >> 6, k = idx & 63;
        xs[r][k] = x[(rowbase + r) * IND + k];
    }
    __syncthreads();

    const float* Wcol;
    int stride;
    if (t < 128)      { Wcol = Wq + t;          stride = 128; }
    else if (t < 256) { Wcol = Wk + (t - 128);  stride = 128; }
    else              { Wcol = Wv + (t - 256);  stride = 64;  }

    float w[64];
#pragma unroll
    for (int k = 0; k < 64; k++) w[k] = Wcol[(size_t)k * stride];

    __half* htcol = g_Hth + ((size_t)b * CTOT + t) * NN + rb * 64;

    const float4* xs4 = (const float4*)&xs[0][0];
    for (int r = 0; r < 64; r++) {
        float acc = 0.f;
#pragma unroll
        for (int kq = 0; kq < 16; kq++) {
            float4 xv = xs4[r * 16 + kq];
            acc += xv.x * w[kq * 4 + 0];
            acc += xv.y * w[kq * 4 + 1];
            acc += xv.z * w[kq * 4 + 2];
            acc += xv.w * w[kq * 4 + 3];
        }
        float v = g_deg[rowbase + r] * acc;
        g_H[(rowbase + r) * CTOT + t] = v;
        htcol[r] = __float2half_rn(v);
    }
}

// ---------------- kernel C: fp16 TC GCN GEMM, 64x320 tiles (adj read ONCE) --
// C = diag(d) * (adjh @ H' + (1-diag)*H'_row) + bias, routed to Q/K/V.
// CTA 64(M) x 320(N), K step 32. 16 warps = 2(m) x 8(n); warp 32 x 40 (5 frags).
#define AST2 40                          // halves per smem row (80 B)
#define GA3 (64 * AST2)                  // A stage: 2560 halves (5120 B)
#define GB3 (320 * AST2)                 // B stage: 12800 halves (25600 B)
#define GSTG3B ((GA3 + GB3) * 2)         // 30720 B per stage
#define SMEM_C (3 * GSTG3B)              // 92160 B

__global__ void __launch_bounds__(512, 2) gcn_gemm_f16(const float* __restrict__ bq,
                                                       const float* __restrict__ bk,
                                                       const float* __restrict__ bv,
                                                       float* __restrict__ outV) {
    extern __shared__ __half smh[];
    uint32_t sbase = smem_u32(smh);

    int b  = blockIdx.y;
    int mt = blockIdx.x;     // 0..15 -> 64-row tiles
    int t  = threadIdx.x;
    int wid = t >> 5, lane = t & 31;
    int g = lane >> 2, tg = lane & 3;
    int wm = wid >> 3;       // 0..1  (32-row m tiles)
    int wn = wid & 7;        // 0..7  (40-col n tiles)

    const __half* adjbh = g_adjh + (size_t)b * NN * NN + (size_t)(mt * 64) * NN;
    const __half* Hthb  = g_Hth + (size_t)b * CTOT * NN;
    const float*  Hb    = g_H + (size_t)b * NN * CTOT;

    // staging: 1536 16B-chunks/stage (A: 256, B: 1280) -> 3 per thread
    const __half* csrc[3];
    uint32_t cdst[3];
#pragma unroll
    for (int i = 0; i < 3; i++) {
        int c = t + i * 512;
        if (c < 256) {                       // A chunk
            int r = c >> 2, q = c & 3;
            csrc[i] = adjbh + (size_t)r * NN + q * 8;
            cdst[i] = sbase + (uint32_t)(r * 80 + q * 16);
        } else {                             // B chunk
            int c2 = c - 256;
            int r = c2 >> 2, q = c2 & 3;
            csrc[i] = Hthb + (size_t)r * NN + q * 8;
            cdst[i] = sbase + (uint32_t)(GA3 * 2 + r * 80 + q * 16);
        }
    }

    // ldmatrix per-lane byte offsets
    int rowin = lane & 7, matlo = (lane >> 3) & 1, mathi = lane >> 4;
    uint32_t a_off = (uint32_t)(((wm * 32 + rowin + 8 * matlo) * AST2 + 8 * mathi) * 2);
    uint32_t b_off4 = (uint32_t)(GA3 * 2 +
                      ((wn * 40 + (lane >> 3) * 8 + rowin) * AST2) * 2);
    uint32_t b_off2 = (uint32_t)(GA3 * 2 +
                      ((wn * 40 + 32 + (lane & 7)) * AST2 + ((lane >> 3) & 1) * 8) * 2);

#define GCN_ISSUE(KT)                                                          \
    {                                                                          \
        int _kt = (KT);                                                        \
        uint32_t off = (uint32_t)(_kt % 3) * GSTG3B;                           \
        cp16(cdst[0] + off, csrc[0] + _kt * 32);                               \
        cp16(cdst[1] + off, csrc[1] + _kt * 32);                               \
        cp16(cdst[2] + off, csrc[2] + _kt * 32);                               \
        asm volatile("cp.async.commit_group;" ::: "memory");                   \
    }

    float acc[2][5][4];
#pragma unroll
    for (int m = 0; m < 2; m++)
#pragma unroll
        for (int n = 0; n < 5; n++)
#pragma unroll
            for (int e = 0; e < 4; e++) acc[m][n][e] = 0.f;

    GCN_ISSUE(0);
    GCN_ISSUE(1);

    for (int kt = 0; kt < 32; kt++) {
        if (kt + 2 < 32) {
            GCN_ISSUE(kt + 2);
        } else {
            asm volatile("cp.async.commit_group;" ::: "memory");  // uniform count
        }
        asm volatile("cp.async.wait_group 2;" ::: "memory");      // stage kt done
        __syncthreads();

        uint32_t stg = sbase + (uint32_t)(kt % 3) * GSTG3B;
#pragma unroll
        for (int ks = 0; ks < 2; ks++) {
            uint32_t kbb = (uint32_t)(ks * 32);   // ks*16 halves in bytes
            uint32_t a[2][4];
            ldsm_x4(a[0][0], a[0][1], a[0][2], a[0][3], stg + a_off + kbb);
            ldsm_x4(a[1][0], a[1][1], a[1][2], a[1][3],
                    stg + a_off + (uint32_t)(16 * AST2 * 2) + kbb);
            uint32_t b0[4], b1[4], b0x, b1x;
            ldsm_x4(b0[0], b0[1], b0[2], b0[3], stg + b_off4 + kbb);
            ldsm_x4(b1[0], b1[1], b1[2], b1[3], stg + b_off4 + kbb + 16);
            ldsm_x2(b0x, b1x, stg + b_off2 + kbb);
#pragma unroll
            for (int n = 0; n < 4; n++)
#pragma unroll
                for (int m = 0; m < 2; m++)
                    mma_f16(acc[m][n], a[m][0], a[m][1], a[m][2], a[m][3],
                            b0[n], b1[n]);
#pragma unroll
            for (int m = 0; m < 2; m++)
                mma_f16(acc[m][4], a[m][0], a[m][1], a[m][2], a[m][3], b0x, b1x);
        }
        __syncthreads();
    }
    asm volatile("cp.async.wait_group 0;" ::: "memory");          // drain

    // epilogue: route per 8-col fragment to Q(half, x1/8) / K(half) / V(fp32)
#pragma unroll
    for (int m = 0; m < 2; m++) {
#pragma unroll
        for (int rr = 0; rr < 2; rr++) {
            int i = mt * 64 + wm * 32 + m * 16 + rr * 8 + g;
            size_t gi = (size_t)b * NN + i;
            float d    = g_deg[gi];
            float corr = 1.0f - g_diag[gi];
            const float* Hrow = Hb + (size_t)i * CTOT;
#pragma unroll
            for (int n = 0; n < 5; n++) {
                int jg = wn * 40 + n * 8 + 2 * tg;
                float2 h2 = *(const float2*)(Hrow + jg);
                float v0 = d * (acc[m][n][rr * 2 + 0] + corr * h2.x);
                float v1 = d * (acc[m][n][rr * 2 + 1] + corr * h2.y);
                if (jg < 128) {
                    v0 = (v0 + bq[jg]) * 0.125f;
                    v1 = (v1 + bq[jg + 1]) * 0.125f;
                    *(half2*)(g_Qh + gi * ATTN + jg) = __floats2half2_rn(v0, v1);
                } else if (jg < 256) {
                    v0 += bk[jg - 128];
                    v1 += bk[jg - 127];
                    *(half2*)(g_Kh + gi * ATTN + (jg - 128)) = __floats2half2_rn(v0, v1);
                } else {
                    float2 ov;
                    ov.x = v0 + bv[jg - 256];
                    ov.y = v1 + bv[jg - 255];
                    *(float2*)(outV + gi * OUTD + (jg - 256)) = ov;
                }
            }
        }
    }
}

// ---------------- kernel D: fp16 TC attn: A = sym(mean_h tanh(Qh Khᵀ)) ------
// (R12 version, unchanged)
#define QSH 136                // half stride: 68 words -> conflict-free LDSM
#define TS 65

__device__ __forceinline__ void load_tile_async(__half* dst, const __half* __restrict__ src,
                                                int t) {
    uint32_t base = smem_u32(dst);
#pragma unroll
    for (int i = 0; i < 4; i++) {
        int idx = t + i * 256;
        int r = idx >> 4, q = idx & 15;                 // 16 x 16B per row
        cp16(base + (uint32_t)(r * QSH * 2 + q * 16), src + r * ATTN + q * 8);
    }
}

__device__ __forceinline__ void attn_compute(uint32_t Qu, uint32_t Ku,
                                             uint32_t a_off, uint32_t b_off,
                                             float out[4][4]) {
#pragma unroll
    for (int n = 0; n < 4; n++)
#pragma unroll
        for (int e = 0; e < 4; e++) out[n][e] = 0.f;

#pragma unroll
    for (int h = 0; h < 4; h++) {
        float acc[4][4];
#pragma unroll
        for (int n = 0; n < 4; n++)
#pragma unroll
            for (int e = 0; e < 4; e++) acc[n][e] = 0.f;

#pragma unroll
        for (int ks = 0; ks < 2; ks++) {
            uint32_t kbb = (uint32_t)((h * 32 + ks * 16) * 2);
            uint32_t a0, a1, a2, a3;
            ldsm_x4(a0, a1, a2, a3, Qu + a_off + kbb);
            uint32_t b0[4], b1[4];
            ldsm_x4(b0[0], b0[1], b0[2], b0[3], Ku + b_off + kbb);
            ldsm_x4(b1[0], b1[1], b1[2], b1[3], Ku + b_off + kbb + 16);
#pragma unroll
            for (int n = 0; n < 4; n++)
                mma_f16(acc[n], a0, a1, a2, a3, b0[n], b1[n]);
        }
        // tanh(acc) = 1 - 2/(e^{2x}+1); batch 4 reciprocals per rcp.approx
#pragma unroll
        for (int n = 0; n < 4; n++) {
            float d0, d1, d2, d3;
            {
                float a, e_;
                a = fminf(acc[n][0] * 2.885390082f, 30.0f);
                asm("ex2.approx.f32 %0, %1;" : "=f"(e_) : "f"(a)); d0 = e_ + 1.0f;
                a = fminf(acc[n][1] * 2.885390082f, 30.0f);
                asm("ex2.approx.f32 %0, %1;" : "=f"(e_) : "f"(a)); d1 = e_ + 1.0f;
                a = fminf(acc[n][2] * 2.885390082f, 30.0f);
                asm("ex2.approx.f32 %0, %1;" : "=f"(e_) : "f"(a)); d2 = e_ + 1.0f;
                a = fminf(acc[n][3] * 2.885390082f, 30.0f);
                asm("ex2.approx.f32 %0, %1;" : "=f"(e_) : "f"(a)); d3 = e_ + 1.0f;
            }
            float p01 = d0 * d1, p23 = d2 * d3;
            float r;
            asm("rcp.approx.f32 %0, %1;" : "=f"(r) : "f"(p01 * p23));
            float r01 = r * p23, r23 = r * p01;
            out[n][0] += fmaf(-2.0f, r01 * d1, 1.0f);
            out[n][1] += fmaf(-2.0f, r01 * d0, 1.0f);
            out[n][2] += fmaf(-2.0f, r23 * d3, 1.0f);
            out[n][3] += fmaf(-2.0f, r23 * d2, 1.0f);
        }
    }
#pragma unroll
    for (int n = 0; n < 4; n++)
#pragma unroll
        for (int e = 0; e < 4; e++) out[n][e] *= 0.25f;   // head mean
}

__device__ __forceinline__ void compute_tile(__half* Qs, __half* Ks,
                                             const __half* qsrc, const __half* ksrc,
                                             uint32_t a_off, uint32_t b_off,
                                             int t, float out[4][4]) {
    load_tile_async(Qs, qsrc, t);
    load_tile_async(Ks, ksrc, t);
    asm volatile("cp.async.commit_group;");
    asm volatile("cp.async.wait_group 0;");
    __syncthreads();
    attn_compute(smem_u32(Qs), smem_u32(Ks), a_off, b_off, out);
    __syncthreads();
}

// smem: 2 half tiles (17408 B each) + T1 float (16640 B) = 51456 B
#define SMEM_D (2 * 64 * QSH * 2 + 64 * TS * 4)

__global__ void __launch_bounds__(256, 4) attn_tc(float* __restrict__ outA) {
    extern __shared__ char smd[];
    __half* Qs = (__half*)smd;
    __half* Ks = Qs + 64 * QSH;
    float*  T1 = (float*)(smd + 2 * 64 * QSH * 2);
    float*  C2 = (float*)smd;          // alias: Qs dead after last MMA

    int p = blockIdx.x, b = blockIdx.y;
    int I = 0;
    while (p >= 16 - I) { p -= 16 - I; I++; }
    int J = I + p;

    int t = threadIdx.x;
    int wid = t >> 5, lane = t & 31;
    int g = lane >> 2, tg = lane & 3;
    int wm = wid >> 1, wn = wid & 1;

    int rowin = lane & 7, matlo = (lane >> 3) & 1, mathi = lane >> 4;
    uint32_t a_off = (uint32_t)(((wm * 16 + rowin + 8 * matlo) * QSH + 8 * mathi) * 2);
    uint32_t b_off = (uint32_t)(((wn * 32 + (lane >> 3) * 8 + rowin) * QSH) * 2);

    const __half* qI = g_Qh + ((size_t)b * NN + I * 64) * ATTN;
    const __half* kJ = g_Kh + ((size_t)b * NN + J * 64) * ATTN;

    float o1[4][4];
    compute_tile(Qs, Ks, qI, kJ, a_off, b_off, t, o1);   // raw (I,J)
#pragma unroll
    for (int n = 0; n < 4; n++)
#pragma unroll
        for (int e = 0; e < 4; e++) {
            int r = wm * 16 + g + (e >> 1) * 8;
            int c = wn * 32 + n * 8 + 2 * tg + (e & 1);
            T1[r * TS + c] = o1[n][e];
        }
    __syncthreads();

    if (I == J) {
        for (int idx = t; idx < 4096; idx += 256) {
            int r = idx >> 6, c = idx & 63;
            C2[r * TS + c] = 0.5f * (T1[r * TS + c] + T1[c * TS + r]);
        }
        __syncthreads();
    } else {
        const __half* qJ = g_Qh + ((size_t)b * NN + J * 64) * ATTN;
        const __half* kI = g_Kh + ((size_t)b * NN + I * 64) * ATTN;
        float o2[4][4];
        compute_tile(Qs, Ks, qJ, kI, a_off, b_off, t, o2);  // raw (J,I)
#pragma unroll
        for (int n = 0; n < 4; n++)
#pragma unroll
            for (int e = 0; e < 4; e++) {
                int r = wm * 16 + g + (e >> 1) * 8;
                int c = wn * 32 + n * 8 + 2 * tg + (e & 1);
                C2[r * TS + c] = 0.5f * (o2[n][e] + T1[c * TS + r]);
            }
        __syncthreads();
    }

    float* ob = outA + ((size_t)b * NN + J * 64) * NN + I * 64;
    for (int idx = t; idx < 1024; idx += 256) {
        int r = idx >> 4, cq = idx & 15;
        const float* row = &C2[r * TS + cq * 4];
        float4 v;
        v.x = row[0]; v.y = row[1]; v.z = row[2]; v.w = row[3];
        *(float4*)(ob + (size_t)r * NN + cq * 4) = v;
    }
    if (I != J) {
        float* ob2 = outA + ((size_t)b * NN + I * 64) * NN + J * 64;
        for (int idx = t; idx < 1024; idx += 256) {
            int r = idx >> 4, cq = idx & 15;
            float4 v;
            v.x = C2[(cq * 4 + 0) * TS + r];
            v.y = C2[(cq * 4 + 1) * TS + r];
            v.z = C2[(cq * 4 + 2) * TS + r];
            v.w = C2[(cq * 4 + 3) * TS + r];
            *(float4*)(ob2 + (size_t)r * NN + cq * 4) = v;
        }
    }
}

// ---------------- launch -----------------------------------------------------
extern "C" void kernel_launch(void* const* d_in, const int* in_sizes, int n_in,
                              void* d_out, int out_size) {
    (void)in_sizes; (void)n_in; (void)out_size;
    const float* x   = (const float*)d_in[0];
    const float* adj = (const float*)d_in[1];
    // d_in[2] = flags (unused by reference)
    const float* Wq = (const float*)d_in[3];
    const float* bq = (const float*)d_in[4];
    const float* Wk = (const float*)d_in[5];
    const float* bk = (const float*)d_in[6];
    const float* Wv = (const float*)d_in[7];
    const float* bv = (const float*)d_in[8];

    float* outV = (float*)d_out;                            // [B,N,64]
    float* outA = (float*)d_out + (size_t)BB * NN * OUTD;   // [B,N,N]

    cudaFuncSetAttribute(gcn_gemm_f16,
                         cudaFuncAttributeMaxDynamicSharedMemorySize, SMEM_C);
    cudaFuncSetAttribute(attn_tc,
                         cudaFuncAttributeMaxDynamicSharedMemorySize, SMEM_D);

    deg_kernel<<<(BB * NN) / 8, 256>>>(adj);
    h_kernel<<<dim3(16, BB), 320>>>(x, Wq, Wk, Wv);
    gcn_gemm_f16<<<dim3(16, BB), 512, SMEM_C>>>(bq, bk, bv, outV);
    attn_tc<<<dim3(136, BB), 256, SMEM_D>>>(outA);
}

// round 15
// speedup vs baseline: 1.3621x; 1.3621x over previous
#include <cuda_runtime.h>
#include <cuda_fp16.h>
#include <math.h>
#include <cstdint>

#define BB 32
#define NN 1024
#define IND 64
#define ATTN 128
#define OUTD 64
#define CTOT 320   // Q(128) | K(128) | V(64)

// ---------------- scratch (device globals; no allocations allowed) ----------
__device__ float  g_deg[BB * NN];
__device__ float  g_diag[BB * NN];
__device__ __half g_adjh[(size_t)BB * NN * NN]; // half adj copy, 67 MB
__device__ float  g_H[(size_t)BB * NN * CTOT];  // fp32 row-major (correction term)
__device__ __half g_Hth[(size_t)BB * CTOT * NN];// half, feature-major (GEMM B)
__device__ __half g_Qh[(size_t)BB * NN * ATTN]; // half, PRE-SCALED by 1/8
__device__ __half g_Kh[(size_t)BB * NN * ATTN]; // half

// ---------------- helpers ----------------------------------------------------
__device__ __forceinline__ void mma_f16(float c[4],
                                        uint32_t a0, uint32_t a1, uint32_t a2, uint32_t a3,
                                        uint32_t b0, uint32_t b1) {
    asm volatile(
        "mma.sync.aligned.m16n8k16.row.col.f32.f16.f16.f32 "
        "{%0,%1,%2,%3}, {%4,%5,%6,%7}, {%8,%9}, {%0,%1,%2,%3};\n"
        : "+f"(c[0]), "+f"(c[1]), "+f"(c[2]), "+f"(c[3])
        : "r"(a0), "r"(a1), "r"(a2), "r"(a3), "r"(b0), "r"(b1));
}

__device__ __forceinline__ void ldsm_x4(uint32_t& r0, uint32_t& r1,
                                        uint32_t& r2, uint32_t& r3, uint32_t addr) {
    asm volatile("ldmatrix.sync.aligned.m8n8.x4.shared.b16 {%0,%1,%2,%3}, [%4];"
                 : "=r"(r0), "=r"(r1), "=r"(r2), "=r"(r3) : "r"(addr));
}

__device__ __forceinline__ void cp16(uint32_t dst, const void* src) {
    asm volatile("cp.async.ca.shared.global [%0], [%1], 16;" :: "r"(dst), "l"(src));
}
__device__ __forceinline__ uint32_t smem_u32(const void* p) {
    uint32_t a;
    asm("{ .reg .u64 t; cvta.to.shared.u64 t, %1; cvt.u32.u64 %0, t; }" : "=r"(a) : "l"(p));
    return a;
}
__device__ __forceinline__ uint32_t h2u(__half2 h) {
    return *reinterpret_cast<uint32_t*>(&h);
}

// ---------------- kernel A: degrees + diag + half adj copy -------------------
__global__ void __launch_bounds__(256) deg_kernel(const float* __restrict__ adj) {
    int warp = (blockIdx.x * blockDim.x + threadIdx.x) >> 5;
    int lane = threadIdx.x & 31;
    if (warp >= BB * NN) return;
    const float* row = adj + (size_t)warp * NN;
    const float4* r4 = (const float4*)row;
    __half* hrow = g_adjh + (size_t)warp * NN;
    float s = 0.f;
#pragma unroll
    for (int j = lane; j < NN / 4; j += 32) {
        float4 v = r4[j];
        s += (v.x + v.y) + (v.z + v.w);
        __half2 h01 = __floats2half2_rn(v.x, v.y);
        __half2 h23 = __floats2half2_rn(v.z, v.w);
        uint2 u; u.x = h2u(h01); u.y = h2u(h23);
        *(uint2*)(hrow + 4 * j) = u;
    }
#pragma unroll
    for (int o = 16; o; o >>= 1) s += __shfl_xor_sync(0xffffffffu, s, o);
    if (lane == 0) {
        int i = warp & (NN - 1);
        float dg = row[i];
        float rs = s - dg + 1.0f;
        g_deg[warp]  = rsqrtf(fmaxf(rs, 1.0f));
        g_diag[warp] = dg;
    }
}

// ---------------- kernel B: H' = diag(d) * (x @ [Wq|Wk|Wv]) ------------------
// g_H coalesced fp32; g_Hth written from a REGISTER-HELD column as 8 STG.128
// per thread (was scattered 2B stores -> ~13x effective-traffic cut).
__global__ void __launch_bounds__(320) h_kernel(const float* __restrict__ x,
                                                const float* __restrict__ Wq,
                                                const float* __restrict__ Wk,
                                                const float* __restrict__ Wv) {
    __shared__ float xs[64][IND];
    int b = blockIdx.y;
    int rb = blockIdx.x;
    int t = threadIdx.x;
    size_t rowbase = ((size_t)b * NN + rb * 64);

    for (int idx = t; idx < 64 * IND; idx += 320) {
        int r = idx >> 6, k = idx & 63;
        xs[r][k] = x[(rowbase + r) * IND + k];
    }
    __syncthreads();

    const float* Wcol;
    int stride;
    if (t < 128)      { Wcol = Wq + t;          stride = 128; }
    else if (t < 256) { Wcol = Wk + (t - 128);  stride = 128; }
    else              { Wcol = Wv + (t - 256);  stride = 64;  }

    float w[64];
#pragma unroll
    for (int k = 0; k < 64; k++) w[k] = Wcol[(size_t)k * stride];

    uint32_t colbuf[32];           // 64 halves of this thread's Hth row
    float vprev = 0.f;

    const float4* xs4 = (const float4*)&xs[0][0];
    for (int r = 0; r < 64; r++) {
        float acc = 0.f;
#pragma unroll
        for (int kq = 0; kq < 16; kq++) {
            float4 xv = xs4[r * 16 + kq];
            acc += xv.x * w[kq * 4 + 0];
            acc += xv.y * w[kq * 4 + 1];
            acc += xv.z * w[kq * 4 + 2];
            acc += xv.w * w[kq * 4 + 3];
        }
        float v = g_deg[rowbase + r] * acc;
        g_H[(rowbase + r) * CTOT + t] = v;
        if (r & 1) colbuf[r >> 1] = h2u(__floats2half2_rn(vprev, v));
        else       vprev = v;
    }

    // coalesced-ish Hth write: 8 x 16B per thread, feature-major row
    __half* hrow = g_Hth + ((size_t)b * CTOT + t) * NN + rb * 64;
#pragma unroll
    for (int i = 0; i < 8; i++)
        *(uint4*)(hrow + i * 8) = *(uint4*)&colbuf[i * 4];
}

// ---------------- kernel C: fp16 TC GCN GEMM, cp.async + ldmatrix (R12) -----
// C = diag(d) * (adjh @ H' + (1-diag)*H'_row) + bias, routed to Q/K/V.
// CTA 128(M) x 64(N), K step 32 (2 x k16). 8 warps 4(m) x 2(n); warp 32x32.
#define AST2 40                          // halves per smem row (80 B)
#define GAH (128 * AST2)                 // A stage: 5120 halves
#define GBH (64 * AST2)                  // B stage: 2560 halves
#define GSTGB ((GAH + GBH) * 2)          // 15360 B per stage
#define SMEM_C (3 * GSTGB)               // 46080 B

__global__ void __launch_bounds__(256, 4) gcn_gemm_f16(const float* __restrict__ bq,
                                                       const float* __restrict__ bk,
                                                       const float* __restrict__ bv,
                                                       float* __restrict__ outV) {
    extern __shared__ __half smh[];
    uint32_t sbase = smem_u32(smh);

    int b  = blockIdx.z;
    int mt = blockIdx.y;     // 0..7 -> 128-row tiles
    int cb = blockIdx.x;     // 0..4 -> 64-col tiles of 320
    int t  = threadIdx.x;
    int wid = t >> 5, lane = t & 31;
    int g = lane >> 2, tg = lane & 3;
    int wm = wid >> 1, wn = wid & 1;

    const __half* adjbh = g_adjh + (size_t)b * NN * NN + (size_t)(mt * 128) * NN;
    const __half* Hthb  = g_Hth + ((size_t)b * CTOT + cb * 64) * NN;
    const float*  Hb    = g_H + (size_t)b * NN * CTOT;
    int colbase = cb * 64;

    // staging (cp.async) coords
    int r0 = t >> 2, q0 = t & 3;
    const __half* a_src0 = adjbh + (size_t)r0 * NN + q0 * 8;
    const __half* b_src  = Hthb + (size_t)r0 * NN + q0 * 8;
    uint32_t a_dst0 = sbase + (uint32_t)(r0 * 80 + q0 * 16);
    uint32_t b_dst  = sbase + (uint32_t)(GAH * 2 + r0 * 80 + q0 * 16);

    // ldmatrix per-lane byte offsets
    int rowin = lane & 7, matlo = (lane >> 3) & 1, mathi = lane >> 4;
    uint32_t a_off = (uint32_t)(((wm * 32 + rowin + 8 * matlo) * AST2 + 8 * mathi) * 2);
    uint32_t b_off = (uint32_t)(GAH * 2 + ((wn * 32 + (lane >> 3) * 8 + rowin) * AST2) * 2);

#define GCN_ISSUE(KT)                                                          \
    {                                                                          \
        int _kt = (KT);                                                        \
        uint32_t off = (uint32_t)(_kt % 3) * GSTGB;                            \
        cp16(a_dst0 + off,               a_src0 + _kt * 32);                   \
        cp16(a_dst0 + off + 64 * 80,     a_src0 + (size_t)64 * NN + _kt * 32); \
        cp16(b_dst + off,                b_src + _kt * 32);                    \
        asm volatile("cp.async.commit_group;" ::: "memory");                   \
    }

    float acc[2][4][4];
#pragma unroll
    for (int m = 0; m < 2; m++)
#pragma unroll
        for (int n = 0; n < 4; n++)
#pragma unroll
            for (int e = 0; e < 4; e++) acc[m][n][e] = 0.f;

    GCN_ISSUE(0);
    GCN_ISSUE(1);

    for (int kt = 0; kt < 32; kt++) {
        if (kt + 2 < 32) {
            GCN_ISSUE(kt + 2);
        } else {
            asm volatile("cp.async.commit_group;" ::: "memory");  // uniform count
        }
        asm volatile("cp.async.wait_group 2;" ::: "memory");      // stage kt done
        __syncthreads();

        uint32_t stg = sbase + (uint32_t)(kt % 3) * GSTGB;
#pragma unroll
        for (int ks = 0; ks < 2; ks++) {
            uint32_t kbb = (uint32_t)(ks * 32);   // ks*16 halves in bytes
            uint32_t a[2][4];
            ldsm_x4(a[0][0], a[0][1], a[0][2], a[0][3], stg + a_off + kbb);
            ldsm_x4(a[1][0], a[1][1], a[1][2], a[1][3],
                    stg + a_off + (uint32_t)(16 * AST2 * 2) + kbb);
            uint32_t b0[4], b1[4];
            ldsm_x4(b0[0], b0[1], b0[2], b0[3], stg + b_off + kbb);
            ldsm_x4(b1[0], b1[1], b1[2], b1[3], stg + b_off + kbb + 16);
#pragma unroll
            for (int n = 0; n < 4; n++)
#pragma unroll
                for (int m = 0; m < 2; m++)
                    mma_f16(acc[m][n], a[m][0], a[m][1], a[m][2], a[m][3],
                            b0[n], b1[n]);
        }
        __syncthreads();
    }

    // epilogue: Q/K written as half (Q pre-scaled 1/8); V fp32 to d_out
    __half* dsth = nullptr; float* dstf = nullptr;
    const float* barr; int jb, stride; float pres = 1.0f;
    if (cb < 2)      { dsth = g_Qh + (size_t)b * NN * ATTN; barr = bq; jb = cb * 64;       stride = ATTN; pres = 0.125f; }
    else if (cb < 4) { dsth = g_Kh + (size_t)b * NN * ATTN; barr = bk; jb = (cb - 2) * 64; stride = ATTN; }
    else             { dstf = outV + (size_t)b * NN * OUTD; barr = bv; jb = 0;             stride = OUTD; }

#pragma unroll
    for (int m = 0; m < 2; m++) {
        int rr0 = mt * 128 + wm * 32 + m * 16 + g;
#pragma unroll
        for (int rr = 0; rr < 2; rr++) {
            int i = rr0 + rr * 8;
            size_t gi = (size_t)b * NN + i;
            float d    = g_deg[gi];
            float corr = 1.0f - g_diag[gi];
#pragma unroll
            for (int n = 0; n < 4; n++) {
                int jl = jb + wn * 32 + n * 8 + 2 * tg;
                int jg = colbase + wn * 32 + n * 8 + 2 * tg;
                float2 h2 = *(const float2*)(Hb + (size_t)i * CTOT + jg);
                float v0 = (d * (acc[m][n][rr * 2 + 0] + corr * h2.x) + barr[jl]) * pres;
                float v1 = (d * (acc[m][n][rr * 2 + 1] + corr * h2.y) + barr[jl + 1]) * pres;
                if (dsth) {
                    *(half2*)(dsth + (size_t)i * stride + jl) = __floats2half2_rn(v0, v1);
                } else {
                    float2 ov; ov.x = v0; ov.y = v1;
                    *(float2*)(dstf + (size_t)i * stride + jl) = ov;
                }
            }
        }
    }
}

// ---------------- kernel D: fp16 TC attn: A = sym(mean_h tanh(Qh Khᵀ)) ------
// (R12 version, unchanged)
#define QSH 136                // half stride: 68 words -> conflict-free LDSM
#define TS 65

__device__ __forceinline__ void load_tile_async(__half* dst, const __half* __restrict__ src,
                                                int t) {
    uint32_t base = smem_u32(dst);
#pragma unroll
    for (int i = 0; i < 4; i++) {
        int idx = t + i * 256;
        int r = idx >> 4, q = idx & 15;                 // 16 x 16B per row
        cp16(base + (uint32_t)(r * QSH * 2 + q * 16), src + r * ATTN + q * 8);
    }
}

__device__ __forceinline__ void attn_compute(uint32_t Qu, uint32_t Ku,
                                             uint32_t a_off, uint32_t b_off,
                                             float out[4][4]) {
#pragma unroll
    for (int n = 0; n < 4; n++)
#pragma unroll
        for (int e = 0; e < 4; e++) out[n][e] = 0.f;

#pragma unroll
    for (int h = 0; h < 4; h++) {
        float acc[4][4];
#pragma unroll
        for (int n = 0; n < 4; n++)
#pragma unroll
            for (int e = 0; e < 4; e++) acc[n][e] = 0.f;

#pragma unroll
        for (int ks = 0; ks < 2; ks++) {
            uint32_t kbb = (uint32_t)((h * 32 + ks * 16) * 2);
            uint32_t a0, a1, a2, a3;
            ldsm_x4(a0, a1, a2, a3, Qu + a_off + kbb);
            uint32_t b0[4], b1[4];
            ldsm_x4(b0[0], b0[1], b0[2], b0[3], Ku + b_off + kbb);
            ldsm_x4(b1[0], b1[1], b1[2], b1[3], Ku + b_off + kbb + 16);
#pragma unroll
            for (int n = 0; n < 4; n++)
                mma_f16(acc[n], a0, a1, a2, a3, b0[n], b1[n]);
        }
        // tanh(acc) = 1 - 2/(e^{2x}+1); batch 4 reciprocals per rcp.approx
#pragma unroll
        for (int n = 0; n < 4; n++) {
            float d0, d1, d2, d3;
            {
                float a, e_;
                a = fminf(acc[n][0] * 2.885390082f, 30.0f);
                asm("ex2.approx.f32 %0, %1;" : "=f"(e_) : "f"(a)); d0 = e_ + 1.0f;
                a = fminf(acc[n][1] * 2.885390082f, 30.0f);
                asm("ex2.approx.f32 %0, %1;" : "=f"(e_) : "f"(a)); d1 = e_ + 1.0f;
                a = fminf(acc[n][2] * 2.885390082f, 30.0f);
                asm("ex2.approx.f32 %0, %1;" : "=f"(e_) : "f"(a)); d2 = e_ + 1.0f;
                a = fminf(acc[n][3] * 2.885390082f, 30.0f);
                asm("ex2.approx.f32 %0, %1;" : "=f"(e_) : "f"(a)); d3 = e_ + 1.0f;
            }
            float p01 = d0 * d1, p23 = d2 * d3;
            float r;
            asm("rcp.approx.f32 %0, %1;" : "=f"(r) : "f"(p01 * p23));
            float r01 = r * p23, r23 = r * p01;
            out[n][0] += fmaf(-2.0f, r01 * d1, 1.0f);
            out[n][1] += fmaf(-2.0f, r01 * d0, 1.0f);
            out[n][2] += fmaf(-2.0f, r23 * d3, 1.0f);
            out[n][3] += fmaf(-2.0f, r23 * d2, 1.0f);
        }
    }
#pragma unroll
    for (int n = 0; n < 4; n++)
#pragma unroll
        for (int e = 0; e < 4; e++) out[n][e] *= 0.25f;   // head mean
}

__device__ __forceinline__ void compute_tile(__half* Qs, __half* Ks,
                                             const __half* qsrc, const __half* ksrc,
                                             uint32_t a_off, uint32_t b_off,
                                             int t, float out[4][4]) {
    load_tile_async(Qs, qsrc, t);
    load_tile_async(Ks, ksrc, t);
    asm volatile("cp.async.commit_group;");
    asm volatile("cp.async.wait_group 0;");
    __syncthreads();
    attn_compute(smem_u32(Qs), smem_u32(Ks), a_off, b_off, out);
    __syncthreads();
}

// smem: 2 half tiles (17408 B each) + T1 float (16640 B) = 51456 B
#define SMEM_D (2 * 64 * QSH * 2 + 64 * TS * 4)

__global__ void __launch_bounds__(256, 4) attn_tc(float* __restrict__ outA) {
    extern __shared__ char smd[];
    __half* Qs = (__half*)smd;
    __half* Ks = Qs + 64 * QSH;
    float*  T1 = (float*)(smd + 2 * 64 * QSH * 2);
    float*  C2 = (float*)smd;          // alias: Qs dead after last MMA

    int p = blockIdx.x, b = blockIdx.y;
    int I = 0;
    while (p >= 16 - I) { p -= 16 - I; I++; }
    int J = I + p;

    int t = threadIdx.x;
    int wid = t >> 5, lane = t & 31;
    int g = lane >> 2, tg = lane & 3;
    int wm = wid >> 1, wn = wid & 1;

    int rowin = lane & 7, matlo = (lane >> 3) & 1, mathi = lane >> 4;
    uint32_t a_off = (uint32_t)(((wm * 16 + rowin + 8 * matlo) * QSH + 8 * mathi) * 2);
    uint32_t b_off = (uint32_t)(((wn * 32 + (lane >> 3) * 8 + rowin) * QSH) * 2);

    const __half* qI = g_Qh + ((size_t)b * NN + I * 64) * ATTN;
    const __half* kJ = g_Kh + ((size_t)b * NN + J * 64) * ATTN;

    float o1[4][4];
    compute_tile(Qs, Ks, qI, kJ, a_off, b_off, t, o1);   // raw (I,J)
#pragma unroll
    for (int n = 0; n < 4; n++)
#pragma unroll
        for (int e = 0; e < 4; e++) {
            int r = wm * 16 + g + (e >> 1) * 8;
            int c = wn * 32 + n * 8 + 2 * tg + (e & 1);
            T1[r * TS + c] = o1[n][e];
        }
    __syncthreads();

    if (I == J) {
        for (int idx = t; idx < 4096; idx += 256) {
            int r = idx >> 6, c = idx & 63;
            C2[r * TS + c] = 0.5f * (T1[r * TS + c] + T1[c * TS + r]);
        }
        __syncthreads();
    } else {
        const __half* qJ = g_Qh + ((size_t)b * NN + J * 64) * ATTN;
        const __half* kI = g_Kh + ((size_t)b * NN + I * 64) * ATTN;
        float o2[4][4];
        compute_tile(Qs, Ks, qJ, kI, a_off, b_off, t, o2);  // raw (J,I)
#pragma unroll
        for (int n = 0; n < 4; n++)
#pragma unroll
            for (int e = 0; e < 4; e++) {
                int r = wm * 16 + g + (e >> 1) * 8;
                int c = wn * 32 + n * 8 + 2 * tg + (e & 1);
                C2[r * TS + c] = 0.5f * (o2[n][e] + T1[c * TS + r]);
            }
        __syncthreads();
    }

    float* ob = outA + ((size_t)b * NN + J * 64) * NN + I * 64;
    for (int idx = t; idx < 1024; idx += 256) {
        int r = idx >> 4, cq = idx & 15;
        const float* row = &C2[r * TS + cq * 4];
        float4 v;
        v.x = row[0]; v.y = row[1]; v.z = row[2]; v.w = row[3];
        *(float4*)(ob + (size_t)r * NN + cq * 4) = v;
    }
    if (I != J) {
        float* ob2 = outA + ((size_t)b * NN + I * 64) * NN + J * 64;
        for (int idx = t; idx < 1024; idx += 256) {
            int r = idx >> 4, cq = idx & 15;
            float4 v;
            v.x = C2[(cq * 4 + 0) * TS + r];
            v.y = C2[(cq * 4 + 1) * TS + r];
            v.z = C2[(cq * 4 + 2) * TS + r];
            v.w = C2[(cq * 4 + 3) * TS + r];
            *(float4*)(ob2 + (size_t)r * NN + cq * 4) = v;
        }
    }
}

// ---------------- launch -----------------------------------------------------
extern "C" void kernel_launch(void* const* d_in, const int* in_sizes, int n_in,
                              void* d_out, int out_size) {
    (void)in_sizes; (void)n_in; (void)out_size;
    const float* x   = (const float*)d_in[0];
    const float* adj = (const float*)d_in[1];
    // d_in[2] = flags (unused by reference)
    const float* Wq = (const float*)d_in[3];
    const float* bq = (const float*)d_in[4];
    const float* Wk = (const float*)d_in[5];
    const float* bk = (const float*)d_in[6];
    const float* Wv = (const float*)d_in[7];
    const float* bv = (const float*)d_in[8];

    float* outV = (float*)d_out;                            // [B,N,64]
    float* outA = (float*)d_out + (size_t)BB * NN * OUTD;   // [B,N,N]

    cudaFuncSetAttribute(gcn_gemm_f16,
                         cudaFuncAttributeMaxDynamicSharedMemorySize, SMEM_C);
    cudaFuncSetAttribute(attn_tc,
                         cudaFuncAttributeMaxDynamicSharedMemorySize, SMEM_D);

    deg_kernel<<<(BB * NN) / 8, 256>>>(adj);
    h_kernel<<<dim3(16, BB), 320>>>(x, Wq, Wk, Wv);
    gcn_gemm_f16<<<dim3(5, 8, BB), 256, SMEM_C>>>(bq, bk, bv, outV);
    attn_tc<<<dim3(136, BB), 256, SMEM_D>>>(outA);
}

// round 16
// speedup vs baseline: 1.4210x; 1.0432x over previous
#include <cuda_runtime.h>
#include <cuda_fp16.h>
#include <math.h>
#include <cstdint>

#define BB 32
#define NN 1024
#define IND 64
#define ATTN 128
#define OUTD 64
#define CTOT 320   // Q(128) | K(128) | V(64)

// ---------------- scratch (device globals; no allocations allowed) ----------
__device__ float  g_deg[BB * NN];
__device__ float  g_diag[BB * NN];
__device__ __half g_adjh[(size_t)BB * NN * NN]; // half adj copy, 67 MB
__device__ float  g_H[(size_t)BB * NN * CTOT];  // fp32 row-major (correction term)
__device__ __half g_Hth[(size_t)BB * CTOT * NN];// half, feature-major (GEMM B)
__device__ __half g_Qh[(size_t)BB * NN * ATTN]; // half, PRE-SCALED by 1/8
__device__ __half g_Kh[(size_t)BB * NN * ATTN]; // half

// ---------------- helpers ----------------------------------------------------
__device__ __forceinline__ void mma_f16(float c[4],
                                        uint32_t a0, uint32_t a1, uint32_t a2, uint32_t a3,
                                        uint32_t b0, uint32_t b1) {
    asm volatile(
        "mma.sync.aligned.m16n8k16.row.col.f32.f16.f16.f32 "
        "{%0,%1,%2,%3}, {%4,%5,%6,%7}, {%8,%9}, {%0,%1,%2,%3};\n"
        : "+f"(c[0]), "+f"(c[1]), "+f"(c[2]), "+f"(c[3])
        : "r"(a0), "r"(a1), "r"(a2), "r"(a3), "r"(b0), "r"(b1));
}

__device__ __forceinline__ void ldsm_x4(uint32_t& r0, uint32_t& r1,
                                        uint32_t& r2, uint32_t& r3, uint32_t addr) {
    asm volatile("ldmatrix.sync.aligned.m8n8.x4.shared.b16 {%0,%1,%2,%3}, [%4];"
                 : "=r"(r0), "=r"(r1), "=r"(r2), "=r"(r3) : "r"(addr));
}

__device__ __forceinline__ void cp16(uint32_t dst, const void* src) {
    asm volatile("cp.async.ca.shared.global [%0], [%1], 16;" :: "r"(dst), "l"(src));
}
__device__ __forceinline__ uint32_t smem_u32(const void* p) {
    uint32_t a;
    asm("{ .reg .u64 t; cvta.to.shared.u64 t, %1; cvt.u32.u64 %0, t; }" : "=r"(a) : "l"(p));
    return a;
}
__device__ __forceinline__ uint32_t h2u(__half2 h) {
    return *reinterpret_cast<uint32_t*>(&h);
}
__device__ __forceinline__ float fast_tanh_hw(float x) {
    float r;
    asm("tanh.approx.f32 %0, %1;" : "=f"(r) : "f"(x));
    return r;
}

// ---------------- kernel A: degrees + diag + half adj copy -------------------
__global__ void __launch_bounds__(256) deg_kernel(const float* __restrict__ adj) {
    int warp = (blockIdx.x * blockDim.x + threadIdx.x) >> 5;
    int lane = threadIdx.x & 31;
    if (warp >= BB * NN) return;
    const float* row = adj + (size_t)warp * NN;
    const float4* r4 = (const float4*)row;
    __half* hrow = g_adjh + (size_t)warp * NN;
    float s = 0.f;
#pragma unroll
    for (int j = lane; j < NN / 4; j += 32) {
        float4 v = r4[j];
        s += (v.x + v.y) + (v.z + v.w);
        __half2 h01 = __floats2half2_rn(v.x, v.y);
        __half2 h23 = __floats2half2_rn(v.z, v.w);
        uint2 u; u.x = h2u(h01); u.y = h2u(h23);
        *(uint2*)(hrow + 4 * j) = u;
    }
#pragma unroll
    for (int o = 16; o; o >>= 1) s += __shfl_xor_sync(0xffffffffu, s, o);
    if (lane == 0) {
        int i = warp & (NN - 1);
        float dg = row[i];
        float rs = s - dg + 1.0f;
        g_deg[warp]  = rsqrtf(fmaxf(rs, 1.0f));
        g_diag[warp] = dg;
    }
}

// ---------------- kernel B: H' = diag(d) * (x @ [Wq|Wk|Wv]) ------------------
// g_H coalesced fp32; g_Hth written from a register-held column as 8 STG.128.
__global__ void __launch_bounds__(320) h_kernel(const float* __restrict__ x,
                                                const float* __restrict__ Wq,
                                                const float* __restrict__ Wk,
                                                const float* __restrict__ Wv) {
    __shared__ float xs[64][IND];
    int b = blockIdx.y;
    int rb = blockIdx.x;
    int t = threadIdx.x;
    size_t rowbase = ((size_t)b * NN + rb * 64);

    for (int idx = t; idx < 64 * IND; idx += 320) {
        int r = idx >> 6, k = idx & 63;
        xs[r][k] = x[(rowbase + r) * IND + k];
    }
    __syncthreads();

    const float* Wcol;
    int stride;
    if (t < 128)      { Wcol = Wq + t;          stride = 128; }
    else if (t < 256) { Wcol = Wk + (t - 128);  stride = 128; }
    else              { Wcol = Wv + (t - 256);  stride = 64;  }

    float w[64];
#pragma unroll
    for (int k = 0; k < 64; k++) w[k] = Wcol[(size_t)k * stride];

    uint32_t colbuf[32];           // 64 halves of this thread's Hth row
    float vprev = 0.f;

    const float4* xs4 = (const float4*)&xs[0][0];
    for (int r = 0; r < 64; r++) {
        float acc = 0.f;
#pragma unroll
        for (int kq = 0; kq < 16; kq++) {
            float4 xv = xs4[r * 16 + kq];
            acc += xv.x * w[kq * 4 + 0];
            acc += xv.y * w[kq * 4 + 1];
            acc += xv.z * w[kq * 4 + 2];
            acc += xv.w * w[kq * 4 + 3];
        }
        float v = g_deg[rowbase + r] * acc;
        g_H[(rowbase + r) * CTOT + t] = v;
        if (r & 1) colbuf[r >> 1] = h2u(__floats2half2_rn(vprev, v));
        else       vprev = v;
    }

    __half* hrow = g_Hth + ((size_t)b * CTOT + t) * NN + rb * 64;
#pragma unroll
    for (int i = 0; i < 8; i++)
        *(uint4*)(hrow + i * 8) = *(uint4*)&colbuf[i * 4];
}

// ---------------- kernel C: fp16 TC GCN GEMM, cp.async + ldmatrix (R12) -----
// C = diag(d) * (adjh @ H' + (1-diag)*H'_row) + bias, routed to Q/K/V.
// CTA 128(M) x 64(N), K step 32 (2 x k16). 8 warps 4(m) x 2(n); warp 32x32.
#define AST2 40                          // halves per smem row (80 B)
#define GAH (128 * AST2)                 // A stage: 5120 halves
#define GBH (64 * AST2)                  // B stage: 2560 halves
#define GSTGB ((GAH + GBH) * 2)          // 15360 B per stage
#define SMEM_C (3 * GSTGB)               // 46080 B

__global__ void __launch_bounds__(256, 4) gcn_gemm_f16(const float* __restrict__ bq,
                                                       const float* __restrict__ bk,
                                                       const float* __restrict__ bv,
                                                       float* __restrict__ outV) {
    extern __shared__ __half smh[];
    uint32_t sbase = smem_u32(smh);

    int b  = blockIdx.z;
    int mt = blockIdx.y;     // 0..7 -> 128-row tiles
    int cb = blockIdx.x;     // 0..4 -> 64-col tiles of 320
    int t  = threadIdx.x;
    int wid = t >> 5, lane = t & 31;
    int g = lane >> 2, tg = lane & 3;
    int wm = wid >> 1, wn = wid & 1;

    const __half* adjbh = g_adjh + (size_t)b * NN * NN + (size_t)(mt * 128) * NN;
    const __half* Hthb  = g_Hth + ((size_t)b * CTOT + cb * 64) * NN;
    const float*  Hb    = g_H + (size_t)b * NN * CTOT;
    int colbase = cb * 64;

    // staging (cp.async) coords
    int r0 = t >> 2, q0 = t & 3;
    const __half* a_src0 = adjbh + (size_t)r0 * NN + q0 * 8;
    const __half* b_src  = Hthb + (size_t)r0 * NN + q0 * 8;
    uint32_t a_dst0 = sbase + (uint32_t)(r0 * 80 + q0 * 16);
    uint32_t b_dst  = sbase + (uint32_t)(GAH * 2 + r0 * 80 + q0 * 16);

    // ldmatrix per-lane byte offsets
    int rowin = lane & 7, matlo = (lane >> 3) & 1, mathi = lane >> 4;
    uint32_t a_off = (uint32_t)(((wm * 32 + rowin + 8 * matlo) * AST2 + 8 * mathi) * 2);
    uint32_t b_off = (uint32_t)(GAH * 2 + ((wn * 32 + (lane >> 3) * 8 + rowin) * AST2) * 2);

#define GCN_ISSUE(KT)                                                          \
    {                                                                          \
        int _kt = (KT);                                                        \
        uint32_t off = (uint32_t)(_kt % 3) * GSTGB;                            \
        cp16(a_dst0 + off,               a_src0 + _kt * 32);                   \
        cp16(a_dst0 + off + 64 * 80,     a_src0 + (size_t)64 * NN + _kt * 32); \
        cp16(b_dst + off,                b_src + _kt * 32);                    \
        asm volatile("cp.async.commit_group;" ::: "memory");                   \
    }

    float acc[2][4][4];
#pragma unroll
    for (int m = 0; m < 2; m++)
#pragma unroll
        for (int n = 0; n < 4; n++)
#pragma unroll
            for (int e = 0; e < 4; e++) acc[m][n][e] = 0.f;

    GCN_ISSUE(0);
    GCN_ISSUE(1);

    for (int kt = 0; kt < 32; kt++) {
        if (kt + 2 < 32) {
            GCN_ISSUE(kt + 2);
        } else {
            asm volatile("cp.async.commit_group;" ::: "memory");  // uniform count
        }
        asm volatile("cp.async.wait_group 2;" ::: "memory");      // stage kt done
        __syncthreads();

        uint32_t stg = sbase + (uint32_t)(kt % 3) * GSTGB;
#pragma unroll
        for (int ks = 0; ks < 2; ks++) {
            uint32_t kbb = (uint32_t)(ks * 32);   // ks*16 halves in bytes
            uint32_t a[2][4];
            ldsm_x4(a[0][0], a[0][1], a[0][2], a[0][3], stg + a_off + kbb);
            ldsm_x4(a[1][0], a[1][1], a[1][2], a[1][3],
                    stg + a_off + (uint32_t)(16 * AST2 * 2) + kbb);
            uint32_t b0[4], b1[4];
            ldsm_x4(b0[0], b0[1], b0[2], b0[3], stg + b_off + kbb);
            ldsm_x4(b1[0], b1[1], b1[2], b1[3], stg + b_off + kbb + 16);
#pragma unroll
            for (int n = 0; n < 4; n++)
#pragma unroll
                for (int m = 0; m < 2; m++)
                    mma_f16(acc[m][n], a[m][0], a[m][1], a[m][2], a[m][3],
                            b0[n], b1[n]);
        }
        __syncthreads();
    }

    // epilogue: Q/K written as half (Q pre-scaled 1/8); V fp32 to d_out
    __half* dsth = nullptr; float* dstf = nullptr;
    const float* barr; int jb, stride; float pres = 1.0f;
    if (cb < 2)      { dsth = g_Qh + (size_t)b * NN * ATTN; barr = bq; jb = cb * 64;       stride = ATTN; pres = 0.125f; }
    else if (cb < 4) { dsth = g_Kh + (size_t)b * NN * ATTN; barr = bk; jb = (cb - 2) * 64; stride = ATTN; }
    else             { dstf = outV + (size_t)b * NN * OUTD; barr = bv; jb = 0;             stride = OUTD; }

#pragma unroll
    for (int m = 0; m < 2; m++) {
        int rr0 = mt * 128 + wm * 32 + m * 16 + g;
#pragma unroll
        for (int rr = 0; rr < 2; rr++) {
            int i = rr0 + rr * 8;
            size_t gi = (size_t)b * NN + i;
            float d    = g_deg[gi];
            float corr = 1.0f - g_diag[gi];
#pragma unroll
            for (int n = 0; n < 4; n++) {
                int jl = jb + wn * 32 + n * 8 + 2 * tg;
                int jg = colbase + wn * 32 + n * 8 + 2 * tg;
                float2 h2 = *(const float2*)(Hb + (size_t)i * CTOT + jg);
                float v0 = (d * (acc[m][n][rr * 2 + 0] + corr * h2.x) + barr[jl]) * pres;
                float v1 = (d * (acc[m][n][rr * 2 + 1] + corr * h2.y) + barr[jl + 1]) * pres;
                if (dsth) {
                    *(half2*)(dsth + (size_t)i * stride + jl) = __floats2half2_rn(v0, v1);
                } else {
                    float2 ov; ov.x = v0; ov.y = v1;
                    *(float2*)(dstf + (size_t)i * stride + jl) = ov;
                }
            }
        }
    }
}

// ---------------- kernel D: fp16 TC attn: A = sym(mean_h tanh(Qh Khᵀ)) ------
// MUFU.TANH epilogue (tanh.approx.f32): 1 MUFU + 1 add per element.
#define QSH 136                // half stride: 68 words -> conflict-free LDSM
#define TS 65

__device__ __forceinline__ void load_tile_async(__half* dst, const __half* __restrict__ src,
                                                int t) {
    uint32_t base = smem_u32(dst);
#pragma unroll
    for (int i = 0; i < 4; i++) {
        int idx = t + i * 256;
        int r = idx >> 4, q = idx & 15;                 // 16 x 16B per row
        cp16(base + (uint32_t)(r * QSH * 2 + q * 16), src + r * ATTN + q * 8);
    }
}

__device__ __forceinline__ void attn_compute(uint32_t Qu, uint32_t Ku,
                                             uint32_t a_off, uint32_t b_off,
                                             float out[4][4]) {
#pragma unroll
    for (int n = 0; n < 4; n++)
#pragma unroll
        for (int e = 0; e < 4; e++) out[n][e] = 0.f;

#pragma unroll
    for (int h = 0; h < 4; h++) {
        float acc[4][4];
#pragma unroll
        for (int n = 0; n < 4; n++)
#pragma unroll
            for (int e = 0; e < 4; e++) acc[n][e] = 0.f;

#pragma unroll
        for (int ks = 0; ks < 2; ks++) {
            uint32_t kbb = (uint32_t)((h * 32 + ks * 16) * 2);
            uint32_t a0, a1, a2, a3;
            ldsm_x4(a0, a1, a2, a3, Qu + a_off + kbb);
            uint32_t b0[4], b1[4];
            ldsm_x4(b0[0], b0[1], b0[2], b0[3], Ku + b_off + kbb);
            ldsm_x4(b1[0], b1[1], b1[2], b1[3], Ku + b_off + kbb + 16);
#pragma unroll
            for (int n = 0; n < 4; n++)
                mma_f16(acc[n], a0, a1, a2, a3, b0[n], b1[n]);
        }
        // hardware tanh (Q pre-scaled by 1/8, so acc IS the score)
#pragma unroll
        for (int n = 0; n < 4; n++)
#pragma unroll
            for (int e = 0; e < 4; e++)
                out[n][e] += fast_tanh_hw(acc[n][e]);
    }
#pragma unroll
    for (int n = 0; n < 4; n++)
#pragma unroll
        for (int e = 0; e < 4; e++) out[n][e] *= 0.25f;   // head mean
}

__device__ __forceinline__ void compute_tile(__half* Qs, __half* Ks,
                                             const __half* qsrc, const __half* ksrc,
                                             uint32_t a_off, uint32_t b_off,
                                             int t, float out[4][4]) {
    load_tile_async(Qs, qsrc, t);
    load_tile_async(Ks, ksrc, t);
    asm volatile("cp.async.commit_group;");
    asm volatile("cp.async.wait_group 0;");
    __syncthreads();
    attn_compute(smem_u32(Qs), smem_u32(Ks), a_off, b_off, out);
    __syncthreads();
}

// smem: 2 half tiles (17408 B each) + T1 float (16640 B) = 51456 B
#define SMEM_D (2 * 64 * QSH * 2 + 64 * TS * 4)

__global__ void __launch_bounds__(256, 4) attn_tc(float* __restrict__ outA) {
    extern __shared__ char smd[];
    __half* Qs = (__half*)smd;
    __half* Ks = Qs + 64 * QSH;
    float*  T1 = (float*)(smd + 2 * 64 * QSH * 2);
    float*  C2 = (float*)smd;          // alias: Qs dead after last MMA

    int p = blockIdx.x, b = blockIdx.y;
    int I = 0;
    while (p >= 16 - I) { p -= 16 - I; I++; }
    int J = I + p;

    int t = threadIdx.x;
    int wid = t >> 5, lane = t & 31;
    int g = lane >> 2, tg = lane & 3;
    int wm = wid >> 1, wn = wid & 1;

    int rowin = lane & 7, matlo = (lane >> 3) & 1, mathi = lane >> 4;
    uint32_t a_off = (uint32_t)(((wm * 16 + rowin + 8 * matlo) * QSH + 8 * mathi) * 2);
    uint32_t b_off = (uint32_t)(((wn * 32 + (lane >> 3) * 8 + rowin) * QSH) * 2);

    const __half* qI = g_Qh + ((size_t)b * NN + I * 64) * ATTN;
    const __half* kJ = g_Kh + ((size_t)b * NN + J * 64) * ATTN;

    float o1[4][4];
    compute_tile(Qs, Ks, qI, kJ, a_off, b_off, t, o1);   // raw (I,J)
#pragma unroll
    for (int n = 0; n < 4; n++)
#pragma unroll
        for (int e = 0; e < 4; e++) {
            int r = wm * 16 + g + (e >> 1) * 8;
            int c = wn * 32 + n * 8 + 2 * tg + (e & 1);
            T1[r * TS + c] = o1[n][e];
        }
    __syncthreads();

    if (I == J) {
        for (int idx = t; idx < 4096; idx += 256) {
            int r = idx >> 6, c = idx & 63;
            C2[r * TS + c] = 0.5f * (T1[r * TS + c] + T1[c * TS + r]);
        }
        __syncthreads();
    } else {
        const __half* qJ = g_Qh + ((size_t)b * NN + J * 64) * ATTN;
        const __half* kI = g_Kh + ((size_t)b * NN + I * 64) * ATTN;
        float o2[4][4];
        compute_tile(Qs, Ks, qJ, kI, a_off, b_off, t, o2);  // raw (J,I)
#pragma unroll
        for (int n = 0; n < 4; n++)
#pragma unroll
            for (int e = 0; e < 4; e++) {
                int r = wm * 16 + g + (e >> 1) * 8;
                int c = wn * 32 + n * 8 + 2 * tg + (e & 1);
                C2[r * TS + c] = 0.5f * (o2[n][e] + T1[c * TS + r]);
            }
        __syncthreads();
    }

    float* ob = outA + ((size_t)b * NN + J * 64) * NN + I * 64;
    for (int idx = t; idx < 1024; idx += 256) {
        int r = idx >> 4, cq = idx & 15;
        const float* row = &C2[r * TS + cq * 4];
        float4 v;
        v.x = row[0]; v.y = row[1]; v.z = row[2]; v.w = row[3];
        *(float4*)(ob + (size_t)r * NN + cq * 4) = v;
    }
    if (I != J) {
        float* ob2 = outA + ((size_t)b * NN + I * 64) * NN + J * 64;
        for (int idx = t; idx < 1024; idx += 256) {
            int r = idx >> 4, cq = idx & 15;
            float4 v;
            v.x = C2[(cq * 4 + 0) * TS + r];
            v.y = C2[(cq * 4 + 1) * TS + r];
            v.z = C2[(cq * 4 + 2) * TS + r];
            v.w = C2[(cq * 4 + 3) * TS + r];
            *(float4*)(ob2 + (size_t)r * NN + cq * 4) = v;
        }
    }
}

// ---------------- launch -----------------------------------------------------
extern "C" void kernel_launch(void* const* d_in, const int* in_sizes, int n_in,
                              void* d_out, int out_size) {
    (void)in_sizes; (void)n_in; (void)out_size;
    const float* x   = (const float*)d_in[0];
    const float* adj = (const float*)d_in[1];
    // d_in[2] = flags (unused by reference)
    const float* Wq = (const float*)d_in[3];
    const float* bq = (const float*)d_in[4];
    const float* Wk = (const float*)d_in[5];
    const float* bk = (const float*)d_in[6];
    const float* Wv = (const float*)d_in[7];
    const float* bv = (const float*)d_in[8];

    float* outV = (float*)d_out;                            // [B,N,64]
    float* outA = (float*)d_out + (size_t)BB * NN * OUTD;   // [B,N,N]

    cudaFuncSetAttribute(gcn_gemm_f16,
                         cudaFuncAttributeMaxDynamicSharedMemorySize, SMEM_C);
    cudaFuncSetAttribute(attn_tc,
                         cudaFuncAttributeMaxDynamicSharedMemorySize, SMEM_D);

    deg_kernel<<<(BB * NN) / 8, 256>>>(adj);
    h_kernel<<<dim3(16, BB), 320>>>(x, Wq, Wk, Wv);
    gcn_gemm_f16<<<dim3(5, 8, BB), 256, SMEM_C>>>(bq, bk, bv, outV);
    attn_tc<<<dim3(136, BB), 256, SMEM_D>>>(outA);
}

// round 17
// speedup vs baseline: 1.5135x; 1.0651x over previous
#include <cuda_runtime.h>
#include <cuda_fp16.h>
#include <math.h>
#include <cstdint>

#define BB 32
#define NN 1024
#define IND 64
#define ATTN 128
#define OUTD 64
#define CTOT 320   // Q(128) | K(128) | V(64)

// ---------------- scratch (device globals; no allocations allowed) ----------
__device__ float  g_deg[BB * NN];
__device__ float  g_diag[BB * NN];
__device__ __half g_adjh[(size_t)BB * NN * NN]; // half adj copy, 67 MB
__device__ __half g_Hh[(size_t)BB * NN * CTOT]; // half row-major (correction term)
__device__ __half g_Hth[(size_t)BB * CTOT * NN];// half, feature-major (GEMM B)
__device__ __half g_Qh[(size_t)BB * NN * ATTN]; // half, PRE-SCALED by 1/8
__device__ __half g_Kh[(size_t)BB * NN * ATTN]; // half

// ---------------- helpers ----------------------------------------------------
__device__ __forceinline__ void mma_f16(float c[4],
                                        uint32_t a0, uint32_t a1, uint32_t a2, uint32_t a3,
                                        uint32_t b0, uint32_t b1) {
    asm volatile(
        "mma.sync.aligned.m16n8k16.row.col.f32.f16.f16.f32 "
        "{%0,%1,%2,%3}, {%4,%5,%6,%7}, {%8,%9}, {%0,%1,%2,%3};\n"
        : "+f"(c[0]), "+f"(c[1]), "+f"(c[2]), "+f"(c[3])
        : "r"(a0), "r"(a1), "r"(a2), "r"(a3), "r"(b0), "r"(b1));
}

__device__ __forceinline__ void ldsm_x4(uint32_t& r0, uint32_t& r1,
                                        uint32_t& r2, uint32_t& r3, uint32_t addr) {
    asm volatile("ldmatrix.sync.aligned.m8n8.x4.shared.b16 {%0,%1,%2,%3}, [%4];"
                 : "=r"(r0), "=r"(r1), "=r"(r2), "=r"(r3) : "r"(addr));
}

__device__ __forceinline__ void cp16(uint32_t dst, const void* src) {
    asm volatile("cp.async.cg.shared.global [%0], [%1], 16;" :: "r"(dst), "l"(src));
}
__device__ __forceinline__ uint32_t smem_u32(const void* p) {
    uint32_t a;
    asm("{ .reg .u64 t; cvta.to.shared.u64 t, %1; cvt.u32.u64 %0, t; }" : "=r"(a) : "l"(p));
    return a;
}
__device__ __forceinline__ uint32_t h2u(__half2 h) {
    return *reinterpret_cast<uint32_t*>(&h);
}
__device__ __forceinline__ float fast_tanh_hw(float x) {
    float r;
    asm("tanh.approx.f32 %0, %1;" : "=f"(r) : "f"(x));
    return r;
}

// ---------------- kernel A: degrees + diag + half adj copy -------------------
__global__ void __launch_bounds__(256) deg_kernel(const float* __restrict__ adj) {
    int warp = (blockIdx.x * blockDim.x + threadIdx.x) >> 5;
    int lane = threadIdx.x & 31;
    if (warp >= BB * NN) return;
    const float* row = adj + (size_t)warp * NN;
    const float4* r4 = (const float4*)row;
    __half* hrow = g_adjh + (size_t)warp * NN;
    float s = 0.f;
#pragma unroll
    for (int j = lane; j < NN / 4; j += 32) {
        float4 v = r4[j];
        s += (v.x + v.y) + (v.z + v.w);
        __half2 h01 = __floats2half2_rn(v.x, v.y);
        __half2 h23 = __floats2half2_rn(v.z, v.w);
        uint2 u; u.x = h2u(h01); u.y = h2u(h23);
        *(uint2*)(hrow + 4 * j) = u;
    }
#pragma unroll
    for (int o = 16; o; o >>= 1) s += __shfl_xor_sync(0xffffffffu, s, o);
    if (lane == 0) {
        int i = warp & (NN - 1);
        float dg = row[i];
        float rs = s - dg + 1.0f;
        g_deg[warp]  = rsqrtf(fmaxf(rs, 1.0f));
        g_diag[warp] = dg;
    }
}

// ---------------- kernel B: H' = diag(d) * (x @ [Wq|Wk|Wv]) ------------------
// Both H' copies stored half: g_Hh row-major (correction), g_Hth feature-major.
__global__ void __launch_bounds__(320) h_kernel(const float* __restrict__ x,
                                                const float* __restrict__ Wq,
                                                const float* __restrict__ Wk,
                                                const float* __restrict__ Wv) {
    __shared__ float xs[64][IND];
    int b = blockIdx.y;
    int rb = blockIdx.x;
    int t = threadIdx.x;
    size_t rowbase = ((size_t)b * NN + rb * 64);

    for (int idx = t; idx < 64 * IND; idx += 320) {
        int r = idx >> 6, k = idx & 63;
        xs[r][k] = x[(rowbase + r) * IND + k];
    }
    __syncthreads();

    const float* Wcol;
    int stride;
    if (t < 128)      { Wcol = Wq + t;          stride = 128; }
    else if (t < 256) { Wcol = Wk + (t - 128);  stride = 128; }
    else              { Wcol = Wv + (t - 256);  stride = 64;  }

    float w[64];
#pragma unroll
    for (int k = 0; k < 64; k++) w[k] = Wcol[(size_t)k * stride];

    uint32_t colbuf[32];           // 64 halves of this thread's Hth row
    float vprev = 0.f;

    const float4* xs4 = (const float4*)&xs[0][0];
    for (int r = 0; r < 64; r++) {
        float acc = 0.f;
#pragma unroll
        for (int kq = 0; kq < 16; kq++) {
            float4 xv = xs4[r * 16 + kq];
            acc += xv.x * w[kq * 4 + 0];
            acc += xv.y * w[kq * 4 + 1];
            acc += xv.z * w[kq * 4 + 2];
            acc += xv.w * w[kq * 4 + 3];
        }
        float v = g_deg[rowbase + r] * acc;
        __half hv = __float2half_rn(v);
        g_Hh[(rowbase + r) * CTOT + t] = hv;
        uint32_t packed;
        {
            __half2 hp;
            if (r & 1) { hp = __halves2half2(__float2half_rn(vprev), hv);
                         colbuf[r >> 1] = h2u(hp); }
            else vprev = v;
            (void)packed;
        }
    }

    __half* hrow = g_Hth + ((size_t)b * CTOT + t) * NN + rb * 64;
#pragma unroll
    for (int i = 0; i < 8; i++)
        *(uint4*)(hrow + i * 8) = *(uint4*)&colbuf[i * 4];
}

// ---------------- kernel C: fp16 TC GCN GEMM, cp.async + ldmatrix -----------
// C = diag(d) * (adjh @ H' + (1-diag)*H'_row) + bias, routed to Q/K/V.
// CTA 128(M) x 64(N), K step 32 (2 x k16). 8 warps 4(m) x 2(n); warp 32x32.
#define AST2 40                          // halves per smem row (80 B)
#define GAH (128 * AST2)                 // A stage: 5120 halves
#define GBH (64 * AST2)                  // B stage: 2560 halves
#define GSTGB ((GAH + GBH) * 2)          // 15360 B per stage
#define SMEM_C (3 * GSTGB)               // 46080 B

__global__ void __launch_bounds__(256, 4) gcn_gemm_f16(const float* __restrict__ bq,
                                                       const float* __restrict__ bk,
                                                       const float* __restrict__ bv,
                                                       float* __restrict__ outV) {
    extern __shared__ __half smh[];
    uint32_t sbase = smem_u32(smh);

    int b  = blockIdx.z;
    int mt = blockIdx.y;     // 0..7 -> 128-row tiles
    int cb = blockIdx.x;     // 0..4 -> 64-col tiles of 320
    int t  = threadIdx.x;
    int wid = t >> 5, lane = t & 31;
    int g = lane >> 2, tg = lane & 3;
    int wm = wid >> 1, wn = wid & 1;

    const __half* adjbh = g_adjh + (size_t)b * NN * NN + (size_t)(mt * 128) * NN;
    const __half* Hthb  = g_Hth + ((size_t)b * CTOT + cb * 64) * NN;
    const __half* Hhb   = g_Hh + (size_t)b * NN * CTOT;
    int colbase = cb * 64;

    // staging (cp.async) coords
    int r0 = t >> 2, q0 = t & 3;
    const __half* a_src0 = adjbh + (size_t)r0 * NN + q0 * 8;
    const __half* b_src  = Hthb + (size_t)r0 * NN + q0 * 8;
    uint32_t a_dst0 = sbase + (uint32_t)(r0 * 80 + q0 * 16);
    uint32_t b_dst  = sbase + (uint32_t)(GAH * 2 + r0 * 80 + q0 * 16);

    // ldmatrix per-lane byte offsets
    int rowin = lane & 7, matlo = (lane >> 3) & 1, mathi = lane >> 4;
    uint32_t a_off = (uint32_t)(((wm * 32 + rowin + 8 * matlo) * AST2 + 8 * mathi) * 2);
    uint32_t b_off = (uint32_t)(GAH * 2 + ((wn * 32 + (lane >> 3) * 8 + rowin) * AST2) * 2);

#define GCN_ISSUE(KT)                                                          \
    {                                                                          \
        int _kt = (KT);                                                        \
        uint32_t off = (uint32_t)(_kt % 3) * GSTGB;                            \
        cp16(a_dst0 + off,               a_src0 + _kt * 32);                   \
        cp16(a_dst0 + off + 64 * 80,     a_src0 + (size_t)64 * NN + _kt * 32); \
        cp16(b_dst + off,                b_src + _kt * 32);                    \
        asm volatile("cp.async.commit_group;" ::: "memory");                   \
    }

    float acc[2][4][4];
#pragma unroll
    for (int m = 0; m < 2; m++)
#pragma unroll
        for (int n = 0; n < 4; n++)
#pragma unroll
            for (int e = 0; e < 4; e++) acc[m][n][e] = 0.f;

    GCN_ISSUE(0);
    GCN_ISSUE(1);

    for (int kt = 0; kt < 32; kt++) {
        if (kt + 2 < 32) {
            GCN_ISSUE(kt + 2);
        } else {
            asm volatile("cp.async.commit_group;" ::: "memory");  // uniform count
        }
        asm volatile("cp.async.wait_group 2;" ::: "memory");      // stage kt done
        __syncthreads();

        uint32_t stg = sbase + (uint32_t)(kt % 3) * GSTGB;
#pragma unroll
        for (int ks = 0; ks < 2; ks++) {
            uint32_t kbb = (uint32_t)(ks * 32);   // ks*16 halves in bytes
            uint32_t a[2][4];
            ldsm_x4(a[0][0], a[0][1], a[0][2], a[0][3], stg + a_off + kbb);
            ldsm_x4(a[1][0], a[1][1], a[1][2], a[1][3],
                    stg + a_off + (uint32_t)(16 * AST2 * 2) + kbb);
            uint32_t b0[4], b1[4];
            ldsm_x4(b0[0], b0[1], b0[2], b0[3], stg + b_off + kbb);
            ldsm_x4(b1[0], b1[1], b1[2], b1[3], stg + b_off + kbb + 16);
#pragma unroll
            for (int n = 0; n < 4; n++)
#pragma unroll
                for (int m = 0; m < 2; m++)
                    mma_f16(acc[m][n], a[m][0], a[m][1], a[m][2], a[m][3],
                            b0[n], b1[n]);
        }
        __syncthreads();
    }

    // epilogue: Q/K written as half (Q pre-scaled 1/8); V fp32 to d_out
    __half* dsth = nullptr; float* dstf = nullptr;
    const float* barr; int jb, stride; float pres = 1.0f;
    if (cb < 2)      { dsth = g_Qh + (size_t)b * NN * ATTN; barr = bq; jb = cb * 64;       stride = ATTN; pres = 0.125f; }
    else if (cb < 4) { dsth = g_Kh + (size_t)b * NN * ATTN; barr = bk; jb = (cb - 2) * 64; stride = ATTN; }
    else             { dstf = outV + (size_t)b * NN * OUTD; barr = bv; jb = 0;             stride = OUTD; }

#pragma unroll
    for (int m = 0; m < 2; m++) {
        int rr0 = mt * 128 + wm * 32 + m * 16 + g;
#pragma unroll
        for (int rr = 0; rr < 2; rr++) {
            int i = rr0 + rr * 8;
            size_t gi = (size_t)b * NN + i;
            float d    = g_deg[gi];
            float corr = 1.0f - g_diag[gi];
#pragma unroll
            for (int n = 0; n < 4; n++) {
                int jl = jb + wn * 32 + n * 8 + 2 * tg;
                int jg = colbase + wn * 32 + n * 8 + 2 * tg;
                __half2 hh = *(const __half2*)(Hhb + (size_t)i * CTOT + jg);
                float2 h2 = __half22float2(hh);
                float v0 = (d * (acc[m][n][rr * 2 + 0] + corr * h2.x) + barr[jl]) * pres;
                float v1 = (d * (acc[m][n][rr * 2 + 1] + corr * h2.y) + barr[jl + 1]) * pres;
                if (dsth) {
                    *(half2*)(dsth + (size_t)i * stride + jl) = __floats2half2_rn(v0, v1);
                } else {
                    float2 ov; ov.x = v0; ov.y = v1;
                    *(float2*)(dstf + (size_t)i * stride + jl) = ov;
                }
            }
        }
    }
}

// ---------------- kernel D: fp16 TC attn: A = sym(mean_h tanh(Qh Khᵀ)) ------
// MUFU.TANH epilogue; cp.async.cg staging (L1 bypass).
#define QSH 136                // half stride: 68 words -> conflict-free LDSM
#define TS 65

__device__ __forceinline__ void load_tile_async(__half* dst, const __half* __restrict__ src,
                                                int t) {
    uint32_t base = smem_u32(dst);
#pragma unroll
    for (int i = 0; i < 4; i++) {
        int idx = t + i * 256;
        int r = idx >> 4, q = idx & 15;                 // 16 x 16B per row
        cp16(base + (uint32_t)(r * QSH * 2 + q * 16), src + r * ATTN + q * 8);
    }
}

__device__ __forceinline__ void attn_compute(uint32_t Qu, uint32_t Ku,
                                             uint32_t a_off, uint32_t b_off,
                                             float out[4][4]) {
#pragma unroll
    for (int n = 0; n < 4; n++)
#pragma unroll
        for (int e = 0; e < 4; e++) out[n][e] = 0.f;

#pragma unroll
    for (int h = 0; h < 4; h++) {
        float acc[4][4];
#pragma unroll
        for (int n = 0; n < 4; n++)
#pragma unroll
            for (int e = 0; e < 4; e++) acc[n][e] = 0.f;

#pragma unroll
        for (int ks = 0; ks < 2; ks++) {
            uint32_t kbb = (uint32_t)((h * 32 + ks * 16) * 2);
            uint32_t a0, a1, a2, a3;
            ldsm_x4(a0, a1, a2, a3, Qu + a_off + kbb);
            uint32_t b0[4], b1[4];
            ldsm_x4(b0[0], b0[1], b0[2], b0[3], Ku + b_off + kbb);
            ldsm_x4(b1[0], b1[1], b1[2], b1[3], Ku + b_off + kbb + 16);
#pragma unroll
            for (int n = 0; n < 4; n++)
                mma_f16(acc[n], a0, a1, a2, a3, b0[n], b1[n]);
        }
        // hardware tanh (Q pre-scaled by 1/8, so acc IS the score)
#pragma unroll
        for (int n = 0; n < 4; n++)
#pragma unroll
            for (int e = 0; e < 4; e++)
                out[n][e] += fast_tanh_hw(acc[n][e]);
    }
#pragma unroll
    for (int n = 0; n < 4; n++)
#pragma unroll
        for (int e = 0; e < 4; e++) out[n][e] *= 0.25f;   // head mean
}

__device__ __forceinline__ void compute_tile(__half* Qs, __half* Ks,
                                             const __half* qsrc, const __half* ksrc,
                                             uint32_t a_off, uint32_t b_off,
                                             int t, float out[4][4]) {
    load_tile_async(Qs, qsrc, t);
    load_tile_async(Ks, ksrc, t);
    asm volatile("cp.async.commit_group;");
    asm volatile("cp.async.wait_group 0;");
    __syncthreads();
    attn_compute(smem_u32(Qs), smem_u32(Ks), a_off, b_off, out);
    __syncthreads();
}

// smem: 2 half tiles (17408 B each) + T1 float (16640 B) = 51456 B
#define SMEM_D (2 * 64 * QSH * 2 + 64 * TS * 4)

__global__ void __launch_bounds__(256, 4) attn_tc(float* __restrict__ outA) {
    extern __shared__ char smd[];
    __half* Qs = (__half*)smd;
    __half* Ks = Qs + 64 * QSH;
    float*  T1 = (float*)(smd + 2 * 64 * QSH * 2);
    float*  C2 = (float*)smd;          // alias: Qs dead after last MMA

    int p = blockIdx.x, b = blockIdx.y;
    int I = 0;
    while (p >= 16 - I) { p -= 16 - I; I++; }
    int J = I + p;

    int t = threadIdx.x;
    int wid = t >> 5, lane = t & 31;
    int g = lane >> 2, tg = lane & 3;
    int wm = wid >> 1, wn = wid & 1;

    int rowin = lane & 7, matlo = (lane >> 3) & 1, mathi = lane >> 4;
    uint32_t a_off = (uint32_t)(((wm * 16 + rowin + 8 * matlo) * QSH + 8 * mathi) * 2);
    uint32_t b_off = (uint32_t)(((wn * 32 + (lane >> 3) * 8 + rowin) * QSH) * 2);

    const __half* qI = g_Qh + ((size_t)b * NN + I * 64) * ATTN;
    const __half* kJ = g_Kh + ((size_t)b * NN + J * 64) * ATTN;

    float o1[4][4];
    compute_tile(Qs, Ks, qI, kJ, a_off, b_off, t, o1);   // raw (I,J)
#pragma unroll
    for (int n = 0; n < 4; n++)
#pragma unroll
        for (int e = 0; e < 4; e++) {
            int r = wm * 16 + g + (e >> 1) * 8;
            int c = wn * 32 + n * 8 + 2 * tg + (e & 1);
            T1[r * TS + c] = o1[n][e];
        }
    __syncthreads();

    if (I == J) {
        for (int idx = t; idx < 4096; idx += 256) {
            int r = idx >> 6, c = idx & 63;
            C2[r * TS + c] = 0.5f * (T1[r * TS + c] + T1[c * TS + r]);
        }
        __syncthreads();
    } else {
        const __half* qJ = g_Qh + ((size_t)b * NN + J * 64) * ATTN;
        const __half* kI = g_Kh + ((size_t)b * NN + I * 64) * ATTN;
        float o2[4][4];
        compute_tile(Qs, Ks, qJ, kI, a_off, b_off, t, o2);  // raw (J,I)
#pragma unroll
        for (int n = 0; n < 4; n++)
#pragma unroll
            for (int e = 0; e < 4; e++) {
                int r = wm * 16 + g + (e >> 1) * 8;
                int c = wn * 32 + n * 8 + 2 * tg + (e & 1);
                C2[r * TS + c] = 0.5f * (o2[n][e] + T1[c * TS + r]);
            }
        __syncthreads();
    }

    float* ob = outA + ((size_t)b * NN + J * 64) * NN + I * 64;
    for (int idx = t; idx < 1024; idx += 256) {
        int r = idx >> 4, cq = idx & 15;
        const float* row = &C2[r * TS + cq * 4];
        float4 v;
        v.x = row[0]; v.y = row[1]; v.z = row[2]; v.w = row[3];
        *(float4*)(ob + (size_t)r * NN + cq * 4) = v;
    }
    if (I != J) {
        float* ob2 = outA + ((size_t)b * NN + I * 64) * NN + J * 64;
        for (int idx = t; idx < 1024; idx += 256) {
            int r = idx >> 4, cq = idx & 15;
            float4 v;
            v.x = C2[(cq * 4 + 0) * TS + r];
            v.y = C2[(cq * 4 + 1) * TS + r];
            v.z = C2[(cq * 4 + 2) * TS + r];
            v.w = C2[(cq * 4 + 3) * TS + r];
            *(float4*)(ob2 + (size_t)r * NN + cq * 4) = v;
        }
    }
}

// ---------------- launch -----------------------------------------------------
extern "C" void kernel_launch(void* const* d_in, const int* in_sizes, int n_in,
                              void* d_out, int out_size) {
    (void)in_sizes; (void)n_in; (void)out_size;
    const float* x   = (const float*)d_in[0];
    const float* adj = (const float*)d_in[1];
    // d_in[2] = flags (unused by reference)
    const float* Wq = (const float*)d_in[3];
    const float* bq = (const float*)d_in[4];
    const float* Wk = (const float*)d_in[5];
    const float* bk = (const float*)d_in[6];
    const float* Wv = (const float*)d_in[7];
    const float* bv = (const float*)d_in[8];

    float* outV = (float*)d_out;                            // [B,N,64]
    float* outA = (float*)d_out + (size_t)BB * NN * OUTD;   // [B,N,N]

    cudaFuncSetAttribute(gcn_gemm_f16,
                         cudaFuncAttributeMaxDynamicSharedMemorySize, SMEM_C);
    cudaFuncSetAttribute(attn_tc,
                         cudaFuncAttributeMaxDynamicSharedMemorySize, SMEM_D);

    deg_kernel<<<(BB * NN) / 8, 256>>>(adj);
    h_kernel<<<dim3(16, BB), 320>>>(x, Wq, Wk, Wv);
    gcn_gemm_f16<<<dim3(5, 8, BB), 256, SMEM_C>>>(bq, bk, bv, outV);
    attn_tc<<<dim3(136, BB), 256, SMEM_D>>>(outA);
}